// round 11
// baseline (speedup 1.0000x reference)
#include <cuda_runtime.h>
#include <cstdint>

#define T_LEN 2048
#define F_DIM 32
#define B_TOT 512
#define BT    (B_TOT * T_LEN)          // 1,048,576 rows

typedef unsigned long long U;          // packed f32x2 carrier

// ---------------- scratch (__device__ globals) ------------------------------
__device__ float2 g_gx2[(size_t)BT * 2 * F_DIM];  // (pre_g2r, pre_g2r+1)  536MB
__device__ float  g_yxh[(size_t)BT * 2 * F_DIM];  // out-lin x-half        268MB

// ---------------- packed fp32x2 helpers ------------------------------------
__device__ __forceinline__ U ffma2(U a, U b, U c) {
    U d; asm("fma.rn.f32x2 %0, %1, %2, %3;" : "=l"(d) : "l"(a), "l"(b), "l"(c));
    return d;
}
__device__ __forceinline__ U add2(U a, U b) {
    U d; asm("add.rn.f32x2 %0, %1, %2;" : "=l"(d) : "l"(a), "l"(b));
    return d;
}
__device__ __forceinline__ U pack2(float lo, float hi) {
    U d; asm("mov.b64 %0, {%1, %2};" : "=l"(d) : "f"(lo), "f"(hi));
    return d;
}
__device__ __forceinline__ float2 unpk(U d) {
    float2 r; asm("mov.b64 {%0, %1}, %2;" : "=f"(r.x), "=f"(r.y) : "l"(d));
    return r;
}
__device__ __forceinline__ float sum4(U a, U b) {
    float2 s = unpk(add2(a, b));
    return s.x + s.y;
}

// ---------------- activations (R10-proven: rel_err 7.9e-7) ------------------
__device__ __forceinline__ float tanh_f(float x) {
    float y; asm("tanh.approx.f32 %0, %1;" : "=f"(y) : "f"(x));
    return y;
}
__device__ __forceinline__ float sig_f(float x) {
    return fmaf(tanh_f(0.5f * x), 0.5f, 0.5f);
}
__device__ __forceinline__ float tanh_acc(float x) {   // final output only
    x = fminf(15.0f, fmaxf(-15.0f, x));
    float e = __expf(-2.0f * x);
    return __fdividef(1.0f - e, 1.0f + e);
}

// ============================================================================
// K1: per row (b,t):  gx2[row][r] = (bias2r + Wih[2r]·x, bias2r+1 + Wih[2r+1]·x)
//     yxh[row][r]     = sum_{j in [16r,16r+16)} W_lin[f][2j+1]·x_j (+b_lin if r=0)
//     CTA 256 thr = 4 pairs of warps; 32-row smem tiles, double buffered.
// ============================================================================
__global__ void __launch_bounds__(256, 2)
k1_xpre(const float* __restrict__ x,
        const float* __restrict__ W_ih,
        const float* __restrict__ b_ih,
        const float* __restrict__ b_hh,
        const float* __restrict__ W_lin,
        const float* __restrict__ b_lin)
{
    __shared__ __align__(16) float xs[2][32][F_DIM];   // 8KB
    const int tid = threadIdx.x;
    const int w = tid >> 5, f = tid & 31;
    const int pairId = w >> 1, r = w & 1;
    const int g0 = 2 * r;
    const U ZERO = pack2(0.0f, 0.0f);

    U wa[16], wb[16], wo[8];
    {
        const U* pa = (const U*)(W_ih + (size_t)(g0 * 32 + f) * 32);
        const U* pb = (const U*)(W_ih + (size_t)((g0 + 1) * 32 + f) * 32);
#pragma unroll
        for (int k = 0; k < 16; k++) { wa[k] = pa[k]; wb[k] = pb[k]; }
        const float* pl = W_lin + (size_t)f * 64;
#pragma unroll
        for (int k = 0; k < 4; k++) {
            int i = 4 * r + k;
            wo[2 * k]     = pack2(pl[8 * i + 1], pl[8 * i + 3]);
            wo[2 * k + 1] = pack2(pl[8 * i + 5], pl[8 * i + 7]);
        }
    }
    const float biasA = b_ih[g0 * 32 + f] + b_hh[g0 * 32 + f];
    const float biasB = b_ih[(g0 + 1) * 32 + f] + b_hh[(g0 + 1) * 32 + f];
    const float biasY = r ? 0.0f : b_lin[f];

    const int rowsPerCta = BT / gridDim.x;
    const int base = blockIdx.x * rowsPerCta;
    const int nTiles = rowsPerCta / 32;
    const int srid = tid >> 3, sseg = tid & 7;   // stage: 16B per thread

    {   // stage tile 0
        ulonglong2 v = *(const ulonglong2*)(x + ((size_t)(base + srid) * 32 + sseg * 4));
        *(ulonglong2*)&xs[0][srid][sseg * 4] = v;
    }
    __syncthreads();

    for (int tile = 0; tile < nTiles; tile++) {
        const int cur = tile & 1;
        ulonglong2 nxt;
        const bool have = (tile + 1 < nTiles);
        if (have)
            nxt = *(const ulonglong2*)(x +
                  ((size_t)(base + (tile + 1) * 32 + srid) * 32 + sseg * 4));

        const int row0 = base + tile * 32 + pairId * 8;
#pragma unroll
        for (int rr = 0; rr < 8; rr++) {
            const ulonglong2* xz = (const ulonglong2*)&xs[cur][pairId * 8 + rr][0];
            U a0 = pack2(biasA, 0.f), a1 = ZERO;
            U c0 = pack2(biasB, 0.f), c1 = ZERO;
            U y0 = pack2(biasY, 0.f), y1 = ZERO;
#pragma unroll
            for (int i = 0; i < 8; i++) {
                ulonglong2 v = xz[i];
                a0 = ffma2(wa[2 * i],     v.x, a0);
                a1 = ffma2(wa[2 * i + 1], v.y, a1);
                c0 = ffma2(wb[2 * i],     v.x, c0);
                c1 = ffma2(wb[2 * i + 1], v.y, c1);
            }
#pragma unroll
            for (int k = 0; k < 4; k++) {
                ulonglong2 v = xz[4 * r + k];
                y0 = ffma2(wo[2 * k],     v.x, y0);
                y1 = ffma2(wo[2 * k + 1], v.y, y1);
            }
            const size_t row = (size_t)(row0 + rr);
            g_gx2[(row * 2 + r) * 32 + f] = make_float2(sum4(a0, a1), sum4(c0, c1));
            g_yxh[(row * 2 + r) * 32 + f] = sum4(y0, y1);
        }
        if (have)
            *(ulonglong2*)&xs[cur ^ 1][srid][sseg * 4] = nxt;
        __syncthreads();
    }
}

// ============================================================================
// K2: recurrence. CTA = 1 batch, 64 threads (2 warps). Role w: gates 2w,2w+1
//     + even-out-linear chunk j in [16w,16w+16). gx/yxh streamed via rings.
//     Both warps redundantly compute c/h (identical fp). 2 cheap bars/step.
// ============================================================================
__global__ void __launch_bounds__(64)
k2_recur(const float* __restrict__ W_hh,
         const float* __restrict__ W_lin,
         float* __restrict__ out)
{
    __shared__ __align__(16) float  hb[F_DIM];
    __shared__ __align__(16) float4 exs[2][F_DIM];   // (act0, act1, out_chunk, -)

    const int tid = threadIdx.x;
    const int w = tid >> 5, f = tid & 31;
    const int b = blockIdx.x;
    const U ZERO = pack2(0.0f, 0.0f);

    U whhA[16], whhB[16], wle[8];
    {
        const U* pa = (const U*)(W_hh + (size_t)(2 * w * 32 + f) * 32);
        const U* pb = (const U*)(W_hh + (size_t)((2 * w + 1) * 32 + f) * 32);
#pragma unroll
        for (int k = 0; k < 16; k++) { whhA[k] = pa[k]; whhB[k] = pb[k]; }
        const float* pl = W_lin + (size_t)f * 64;
#pragma unroll
        for (int k = 0; k < 4; k++) {
            wle[2 * k]     = pack2(pl[32 * w + 8 * k],     pl[32 * w + 8 * k + 2]);
            wle[2 * k + 1] = pack2(pl[32 * w + 8 * k + 4], pl[32 * w + 8 * k + 6]);
        }
    }

    const float2* gxp = g_gx2 + ((size_t)b * T_LEN * 2 + w) * 32 + f;  // stride 64/t
    const float*  yxp = g_yxh + ((size_t)b * T_LEN * 2 + w) * 32 + f;  // stride 64/t
    float* op = out + (size_t)b * T_LEN * F_DIM + f;

    float c = 0.0f;
    float2 gr[4];
    float  yrh[4];
#pragma unroll
    for (int k = 0; k < 4; k++) { gr[k] = gxp[(size_t)k * 64]; yrh[k] = yxp[(size_t)k * 64]; }
    if (w == 1) hb[f] = 0.0f;
    __syncthreads();

    for (int tb = 0; tb < T_LEN; tb += 4) {
#pragma unroll
        for (int u = 0; u < 4; u++) {
            const int t = tb + u;

            // ===== phase 1: gate dots over h_{t-1} + even-out chunk =====
            const ulonglong2* hz = (const ulonglong2*)&hb[0];
            float2 gx = gr[t & 3];
            U a0 = pack2(gx.x, 0.f), a1 = ZERO;
            U b0 = pack2(gx.y, 0.f), b1 = ZERO;
#pragma unroll
            for (int i = 0; i < 8; i++) {
                ulonglong2 v = hz[i];
                a0 = ffma2(whhA[2 * i],     v.x, a0);
                a1 = ffma2(whhA[2 * i + 1], v.y, a1);
                b0 = ffma2(whhB[2 * i],     v.x, b0);
                b1 = ffma2(whhB[2 * i + 1], v.y, b1);
            }
            U o0 = ZERO, o1 = ZERO;
#pragma unroll
            for (int k = 0; k < 4; k++) {
                ulonglong2 v = hz[4 * w + k];
                o0 = ffma2(wle[2 * k],     v.x, o0);
                o1 = ffma2(wle[2 * k + 1], v.y, o1);
            }
            float pre0 = sum4(a0, a1);
            float pre1 = sum4(b0, b1);
            float act0 = w ? tanh_f(pre0) : sig_f(pre0);   // g : i
            float act1 = sig_f(pre1);                      // o : f
            float ohs  = sum4(o0, o1) + yrh[(t - 1) & 3];  // t=0: junk, unused
            exs[w][f] = make_float4(act0, act1, ohs, 0.f);

            // ring refills (off critical path)
            {
                int pt = t + 4; if (pt > T_LEN - 1) pt = T_LEN - 1;
                gr[t & 3] = gxp[(size_t)pt * 64];
            }
            if (t > 0) {
                int pt = t + 3; if (pt > T_LEN - 1) pt = T_LEN - 1;
                yrh[(t - 1) & 3] = yxp[(size_t)pt * 64];
            }

            __syncthreads();   // BAR1: acts + chunks published

            // ===== phase 2: redundant c/h; role1 stages h; role0 writes out =====
            float4 oth = exs[w ^ 1][f];
            float gi, gf_, gg, go;
            if (w == 0) { gi = act0; gf_ = act1; gg = oth.x; go = oth.y; }
            else        { gi = oth.x; gf_ = oth.y; gg = act0; go = act1; }
            c = gf_ * c + gi * gg;
            float h = go * tanh_f(c);
            if (w == 1) hb[f] = h;
            else if (t > 0)
                op[(size_t)(t - 1) * F_DIM] = tanh_acc(ohs + oth.z);

            __syncthreads();   // BAR2: h_t visible
        }
    }

    // ---- epilogue: out_{T-1} over final h ----
    {
        const ulonglong2* hz = (const ulonglong2*)&hb[0];
        U o0 = ZERO, o1 = ZERO;
#pragma unroll
        for (int k = 0; k < 4; k++) {
            ulonglong2 v = hz[4 * w + k];
            o0 = ffma2(wle[2 * k],     v.x, o0);
            o1 = ffma2(wle[2 * k + 1], v.y, o1);
        }
        float ohs = sum4(o0, o1) + yrh[(T_LEN - 2) & 3];   // holds yxh[T-1]
        exs[w][f] = make_float4(0.f, 0.f, ohs, 0.f);
        __syncthreads();
        if (w == 0)
            op[(size_t)(T_LEN - 1) * F_DIM] = tanh_acc(exs[0][f].z + exs[1][f].z);
    }
}

// ============================================================================
extern "C" void kernel_launch(void* const* d_in, const int* in_sizes, int n_in,
                              void* d_out, int out_size)
{
    const float* x     = (const float*)d_in[0];
    const float* W_ih  = (const float*)d_in[1];
    const float* W_hh  = (const float*)d_in[2];
    const float* b_ih  = (const float*)d_in[3];
    const float* b_hh  = (const float*)d_in[4];
    const float* W_lin = (const float*)d_in[5];
    const float* b_lin = (const float*)d_in[6];
    float* out = (float*)d_out;

    k1_xpre<<<1024, 256>>>(x, W_ih, b_ih, b_hh, W_lin, b_lin);
    k2_recur<<<B_TOT, 64>>>(W_hh, W_lin, out);
}